// round 4
// baseline (speedup 1.0000x reference)
#include <cuda_runtime.h>
#include <cstdint>

// preds [B=8, N=16, C=4, H=128, W=256] f32, gt [8,4,128,256] f32, out scalar f32
#define CHW        131072
#define NCHW       (16 * CHW)
#define NPIX       1048576
#define GRID       148
#define NTHR       256
#define TILE_PX    1024                 // pixels per tile (4KB per member slice)
#define NTILES     1024                 // NPIX / TILE_PX
#define TILE_B     4096                 // bytes per member slice
#define NSLICE     17                   // 16 preds + gt
#define STAGE_B    (NSLICE * TILE_B)    // 69632 B
#define STAGES     3
#define SMEM_BYTES (STAGES * STAGE_B + 64)   // + barrier space
#define MBAR_OFF   (STAGES * STAGE_B)        // full[0..2], empty[0..2] (8B each)

__device__ float        g_partials[GRID];
__device__ unsigned int g_done = 0;

__device__ __forceinline__ uint32_t smem_u32(const void* p) {
    uint32_t a;
    asm("{ .reg .u64 t; cvta.to.shared.u64 t, %1; cvt.u32.u64 %0, t; }" : "=r"(a) : "l"(p));
    return a;
}
__device__ __forceinline__ void mbar_init(uint32_t m, uint32_t cnt) {
    asm volatile("mbarrier.init.shared.b64 [%0], %1;" :: "r"(m), "r"(cnt) : "memory");
}
__device__ __forceinline__ void mbar_expect_tx(uint32_t m, uint32_t bytes) {
    asm volatile("mbarrier.arrive.expect_tx.shared.b64 _, [%0], %1;" :: "r"(m), "r"(bytes) : "memory");
}
__device__ __forceinline__ void mbar_arrive(uint32_t m) {
    asm volatile("mbarrier.arrive.shared.b64 _, [%0];" :: "r"(m) : "memory");
}
__device__ __forceinline__ void mbar_wait(uint32_t m, uint32_t parity) {
    asm volatile(
        "{\n\t.reg .pred P;\n\t"
        "W%=:\n\t"
        "mbarrier.try_wait.parity.shared.b64 P, [%0], %1, 0x989680;\n\t"
        "@!P bra W%=;\n\t}"
        :: "r"(m), "r"(parity) : "memory");
}
__device__ __forceinline__ void bulk_g2s(uint32_t dst, const void* src, uint32_t bytes, uint32_t mbar) {
    asm volatile(
        "cp.async.bulk.shared::cta.global.mbarrier::complete_tx::bytes [%0], [%1], %2, [%3];"
        :: "r"(dst), "l"(src), "r"(bytes), "r"(mbar) : "memory");
}

__device__ __forceinline__ void cas4(float4 &a, float4 &b) {
    float4 lo, hi;
    lo.x = fminf(a.x, b.x); hi.x = fmaxf(a.x, b.x);
    lo.y = fminf(a.y, b.y); hi.y = fmaxf(a.y, b.y);
    lo.z = fminf(a.z, b.z); hi.z = fmaxf(a.z, b.z);
    lo.w = fminf(a.w, b.w); hi.w = fmaxf(a.w, b.w);
    a = lo; b = hi;
}

// Issue the 17 bulk copies for global tile tg into stage st
__device__ __forceinline__ void issue_tile(const float* preds, const float* gt,
                                           int tg, int st, uint32_t sb) {
    const int b   = tg >> 7;                    // 128 tiles per batch image
    const int chw = (tg & 127) * TILE_PX;
    const uint32_t stage = sb + st * STAGE_B;
    const uint32_t mbar_full = sb + MBAR_OFF + st * 8;
    mbar_expect_tx(mbar_full, NSLICE * TILE_B);
    #pragma unroll
    for (int n = 0; n < 16; n++)
        bulk_g2s(stage + n * TILE_B, preds + b * NCHW + n * CHW + chw, TILE_B, mbar_full);
    bulk_g2s(stage + 16 * TILE_B, gt + b * CHW + chw, TILE_B, mbar_full);
}

__global__ __launch_bounds__(NTHR) void crps_tma(const float* __restrict__ preds,
                                                 const float* __restrict__ gt,
                                                 float* __restrict__ out) {
    extern __shared__ char smem[];
    const uint32_t sb  = smem_u32(smem);
    const int tid = threadIdx.x;
    const int bid = blockIdx.x;

    if (tid == 0) {
        #pragma unroll
        for (int s = 0; s < STAGES; s++) {
            mbar_init(sb + MBAR_OFF + s * 8, 1);              // full: 1 arrive + tx
            mbar_init(sb + MBAR_OFF + 24 + s * 8, NTHR);      // empty: all threads
        }
    }
    __syncthreads();

    const int nt = (NTILES - bid + GRID - 1) / GRID;          // 6 or 7 tiles

    // Prologue: fill up to STAGES stages (stages start empty; no wait needed)
    if (tid == 0) {
        const int pre = nt < STAGES ? nt : STAGES;
        for (int j = 0; j < pre; j++)
            issue_tile(preds, gt, bid + j * GRID, j, sb);
    }

    float acc = 0.f;
    for (int i = 0; i < nt; i++) {
        const int st = i % STAGES;
        mbar_wait(sb + MBAR_OFF + st * 8, (i / STAGES) & 1);  // full

        const char* stage = smem + st * STAGE_B;
        const float4 g = reinterpret_cast<const float4*>(stage + 16 * TILE_B)[tid];
        float4 v[16];
        #pragma unroll
        for (int n = 0; n < 16; n++)
            v[n] = reinterpret_cast<const float4*>(stage + n * TILE_B)[tid];

        // term1
        float4 t1 = make_float4(0.f, 0.f, 0.f, 0.f);
        #pragma unroll
        for (int n = 0; n < 16; n++) {
            t1.x += fabsf(v[n].x - g.x);
            t1.y += fabsf(v[n].y - g.y);
            t1.z += fabsf(v[n].z - g.z);
            t1.w += fabsf(v[n].w - g.w);
        }

        // Green's 16-input 60-comparator sorting network (component-wise)
        cas4(v[0],v[1]);  cas4(v[2],v[3]);  cas4(v[4],v[5]);  cas4(v[6],v[7]);
        cas4(v[8],v[9]);  cas4(v[10],v[11]);cas4(v[12],v[13]);cas4(v[14],v[15]);
        cas4(v[0],v[2]);  cas4(v[4],v[6]);  cas4(v[8],v[10]); cas4(v[12],v[14]);
        cas4(v[1],v[3]);  cas4(v[5],v[7]);  cas4(v[9],v[11]); cas4(v[13],v[15]);
        cas4(v[0],v[4]);  cas4(v[8],v[12]); cas4(v[1],v[5]);  cas4(v[9],v[13]);
        cas4(v[2],v[6]);  cas4(v[10],v[14]);cas4(v[3],v[7]);  cas4(v[11],v[15]);
        cas4(v[0],v[8]);  cas4(v[1],v[9]);  cas4(v[2],v[10]); cas4(v[3],v[11]);
        cas4(v[4],v[12]); cas4(v[5],v[13]); cas4(v[6],v[14]); cas4(v[7],v[15]);
        cas4(v[5],v[10]); cas4(v[6],v[9]);  cas4(v[3],v[12]); cas4(v[13],v[14]);
        cas4(v[7],v[11]); cas4(v[1],v[2]);  cas4(v[4],v[8]);
        cas4(v[1],v[4]);  cas4(v[7],v[13]); cas4(v[2],v[8]);  cas4(v[11],v[14]);
        cas4(v[5],v[6]);  cas4(v[9],v[10]);
        cas4(v[2],v[4]);  cas4(v[11],v[13]);cas4(v[3],v[8]);  cas4(v[7],v[12]);
        cas4(v[6],v[8]);  cas4(v[10],v[12]);cas4(v[3],v[5]);  cas4(v[7],v[9]);
        cas4(v[3],v[4]);  cas4(v[5],v[6]);  cas4(v[7],v[8]);  cas4(v[9],v[10]);
        cas4(v[11],v[12]);
        cas4(v[6],v[7]);  cas4(v[8],v[9]);

        // term2: sum_{i<j}(x_j - x_i) = sum_k (2k-15) x_k over sorted values
        float4 t2 = make_float4(0.f, 0.f, 0.f, 0.f);
        #pragma unroll
        for (int k = 0; k < 16; k++) {
            const float w = (float)(2 * k - 15);
            t2.x = fmaf(w, v[k].x, t2.x);
            t2.y = fmaf(w, v[k].y, t2.y);
            t2.z = fmaf(w, v[k].z, t2.z);
            t2.w = fmaf(w, v[k].w, t2.w);
        }

        const float c1 = 1.0f / (16.0f * (float)NPIX);
        const float c2 = 1.0f / (240.0f * (float)NPIX);
        acc += (t1.x + t1.y + t1.z + t1.w) * c1
             - (t2.x + t2.y + t2.z + t2.w) * c2;

        mbar_arrive(sb + MBAR_OFF + 24 + st * 8);             // empty (release)

        if (tid == 0) {
            const int j = i + STAGES;
            if (j < nt) {
                // wait for empty completion of this stage (relaxed OK: post-wait
                // accesses are async-proxy TMA only); completion #(j/3 - 1)
                mbar_wait(sb + MBAR_OFF + 24 + st * 8, ((j / STAGES) + 1) & 1);
                issue_tile(preds, gt, bid + j * GRID, st, sb);
            }
        }
    }

    // Deterministic block reduction (8 warps)
    #pragma unroll
    for (int o = 16; o > 0; o >>= 1) acc += __shfl_down_sync(0xffffffffu, acc, o);
    __shared__ float s[NTHR / 32];
    if ((tid & 31) == 0) s[tid >> 5] = acc;
    __syncthreads();
    if (tid < 32) {
        float x = (tid < (NTHR / 32)) ? s[tid] : 0.f;
        #pragma unroll
        for (int o = 4; o > 0; o >>= 1) x += __shfl_down_sync(0xffu, x, o);
        if (tid == 0) g_partials[bid] = x;
    }

    // Last-block final reduction (deterministic order; atomic only elects)
    __shared__ bool s_last;
    __threadfence();
    if (tid == 0) {
        unsigned int r = atomicAdd(&g_done, 1u);
        s_last = (r == (unsigned)(GRID - 1));
    }
    __syncthreads();
    if (s_last) {
        float a2 = (tid < GRID) ? __ldcg(&g_partials[tid]) : 0.f;
        #pragma unroll
        for (int o = 16; o > 0; o >>= 1) a2 += __shfl_down_sync(0xffffffffu, a2, o);
        __shared__ float s2[NTHR / 32];
        if ((tid & 31) == 0) s2[tid >> 5] = a2;
        __syncthreads();
        if (tid == 0) {
            out[0] = s2[0] + s2[1] + s2[2] + s2[3] + s2[4] + s2[5] + s2[6] + s2[7];
            g_done = 0;                                       // reset for graph replay
        }
    }
}

extern "C" void kernel_launch(void* const* d_in, const int* in_sizes, int n_in,
                              void* d_out, int out_size) {
    const float* preds = (const float*)d_in[0];
    const float* gt    = (const float*)d_in[1];
    float* out = (float*)d_out;
    (void)in_sizes; (void)n_in; (void)out_size;
    cudaFuncSetAttribute(crps_tma, cudaFuncAttributeMaxDynamicSharedMemorySize, SMEM_BYTES);
    crps_tma<<<GRID, NTHR, SMEM_BYTES>>>(preds, gt, out);
}

// round 5
// speedup vs baseline: 1.0152x; 1.0152x over previous
#include <cuda_runtime.h>
#include <cstdint>

// preds [B=8, N=16, C=4, H=128, W=256] f32, gt [8,4,128,256] f32, out scalar f32
#define CHW        131072
#define NCHW       (16 * CHW)
#define NPIX       1048576
#define GRID       148
#define NTHR       512                  // 16 warps -> 4 warps/SMSP on the consumer
#define TILE_PX    1024                 // pixels per tile; 512 threads * 2 px (float2)
#define NTILES     1024                 // NPIX / TILE_PX
#define TILE_B     4096                 // bytes per member slice
#define NSLICE     17                   // 16 preds + gt
#define STAGE_B    (NSLICE * TILE_B)    // 69632 B
#define STAGES     3
#define SMEM_BYTES (STAGES * STAGE_B + 64)
#define MBAR_OFF   (STAGES * STAGE_B)   // full[0..2] then empty[0..2], 8B each

__device__ float        g_partials[GRID];
__device__ unsigned int g_done = 0;

__device__ __forceinline__ uint32_t smem_u32(const void* p) {
    uint32_t a;
    asm("{ .reg .u64 t; cvta.to.shared.u64 t, %1; cvt.u32.u64 %0, t; }" : "=r"(a) : "l"(p));
    return a;
}
__device__ __forceinline__ void mbar_init(uint32_t m, uint32_t cnt) {
    asm volatile("mbarrier.init.shared.b64 [%0], %1;" :: "r"(m), "r"(cnt) : "memory");
}
__device__ __forceinline__ void mbar_expect_tx(uint32_t m, uint32_t bytes) {
    asm volatile("mbarrier.arrive.expect_tx.shared.b64 _, [%0], %1;" :: "r"(m), "r"(bytes) : "memory");
}
__device__ __forceinline__ void mbar_arrive(uint32_t m) {
    asm volatile("mbarrier.arrive.shared.b64 _, [%0];" :: "r"(m) : "memory");
}
__device__ __forceinline__ void mbar_wait(uint32_t m, uint32_t parity) {
    asm volatile(
        "{\n\t.reg .pred P;\n\t"
        "W%=:\n\t"
        "mbarrier.try_wait.parity.shared.b64 P, [%0], %1, 0x989680;\n\t"
        "@!P bra W%=;\n\t}"
        :: "r"(m), "r"(parity) : "memory");
}
__device__ __forceinline__ void bulk_g2s(uint32_t dst, const void* src, uint32_t bytes, uint32_t mbar) {
    asm volatile(
        "cp.async.bulk.shared::cta.global.mbarrier::complete_tx::bytes [%0], [%1], %2, [%3];"
        :: "r"(dst), "l"(src), "r"(bytes), "r"(mbar) : "memory");
}

__device__ __forceinline__ void cas2(float2 &a, float2 &b) {
    float2 lo, hi;
    lo.x = fminf(a.x, b.x); hi.x = fmaxf(a.x, b.x);
    lo.y = fminf(a.y, b.y); hi.y = fmaxf(a.y, b.y);
    a = lo; b = hi;
}

__device__ __forceinline__ void issue_tile(const float* preds, const float* gt,
                                           int tg, int st, uint32_t sb) {
    const int b   = tg >> 7;                    // 128 tiles per batch image
    const int chw = (tg & 127) * TILE_PX;
    const uint32_t stage = sb + st * STAGE_B;
    const uint32_t mbar_full = sb + MBAR_OFF + st * 8;
    mbar_expect_tx(mbar_full, NSLICE * TILE_B);
    #pragma unroll
    for (int n = 0; n < 16; n++)
        bulk_g2s(stage + n * TILE_B, preds + b * NCHW + n * CHW + chw, TILE_B, mbar_full);
    bulk_g2s(stage + 16 * TILE_B, gt + b * CHW + chw, TILE_B, mbar_full);
}

__global__ __launch_bounds__(NTHR) void crps_tma(const float* __restrict__ preds,
                                                 const float* __restrict__ gt,
                                                 float* __restrict__ out) {
    extern __shared__ char smem[];
    const uint32_t sb  = smem_u32(smem);
    const int tid = threadIdx.x;
    const int bid = blockIdx.x;

    if (tid == 0) {
        #pragma unroll
        for (int s = 0; s < STAGES; s++) {
            mbar_init(sb + MBAR_OFF + s * 8, 1);          // full: expect_tx arrive + tx
            mbar_init(sb + MBAR_OFF + 24 + s * 8, NTHR);  // empty: all threads arrive
        }
    }
    __syncthreads();

    const int nt = (NTILES - bid + GRID - 1) / GRID;      // 6 or 7 tiles

    if (tid == 0) {
        const int pre = nt < STAGES ? nt : STAGES;
        for (int j = 0; j < pre; j++)
            issue_tile(preds, gt, bid + j * GRID, j, sb);
    }

    float acc = 0.f;
    for (int i = 0; i < nt; i++) {
        const int st = i % STAGES;
        mbar_wait(sb + MBAR_OFF + st * 8, (i / STAGES) & 1);   // full

        const char* stage = smem + st * STAGE_B;
        const float2 g = reinterpret_cast<const float2*>(stage + 16 * TILE_B)[tid];
        float2 v[16];
        #pragma unroll
        for (int n = 0; n < 16; n++)
            v[n] = reinterpret_cast<const float2*>(stage + n * TILE_B)[tid];

        // term1: sum |p - g|
        float2 t1 = make_float2(0.f, 0.f);
        #pragma unroll
        for (int n = 0; n < 16; n++) {
            t1.x += fabsf(v[n].x - g.x);
            t1.y += fabsf(v[n].y - g.y);
        }

        // Green's 16-input 60-comparator sorting network (component-wise)
        cas2(v[0],v[1]);  cas2(v[2],v[3]);  cas2(v[4],v[5]);  cas2(v[6],v[7]);
        cas2(v[8],v[9]);  cas2(v[10],v[11]);cas2(v[12],v[13]);cas2(v[14],v[15]);
        cas2(v[0],v[2]);  cas2(v[4],v[6]);  cas2(v[8],v[10]); cas2(v[12],v[14]);
        cas2(v[1],v[3]);  cas2(v[5],v[7]);  cas2(v[9],v[11]); cas2(v[13],v[15]);
        cas2(v[0],v[4]);  cas2(v[8],v[12]); cas2(v[1],v[5]);  cas2(v[9],v[13]);
        cas2(v[2],v[6]);  cas2(v[10],v[14]);cas2(v[3],v[7]);  cas2(v[11],v[15]);
        cas2(v[0],v[8]);  cas2(v[1],v[9]);  cas2(v[2],v[10]); cas2(v[3],v[11]);
        cas2(v[4],v[12]); cas2(v[5],v[13]); cas2(v[6],v[14]); cas2(v[7],v[15]);
        cas2(v[5],v[10]); cas2(v[6],v[9]);  cas2(v[3],v[12]); cas2(v[13],v[14]);
        cas2(v[7],v[11]); cas2(v[1],v[2]);  cas2(v[4],v[8]);
        cas2(v[1],v[4]);  cas2(v[7],v[13]); cas2(v[2],v[8]);  cas2(v[11],v[14]);
        cas2(v[5],v[6]);  cas2(v[9],v[10]);
        cas2(v[2],v[4]);  cas2(v[11],v[13]);cas2(v[3],v[8]);  cas2(v[7],v[12]);
        cas2(v[6],v[8]);  cas2(v[10],v[12]);cas2(v[3],v[5]);  cas2(v[7],v[9]);
        cas2(v[3],v[4]);  cas2(v[5],v[6]);  cas2(v[7],v[8]);  cas2(v[9],v[10]);
        cas2(v[11],v[12]);
        cas2(v[6],v[7]);  cas2(v[8],v[9]);

        // term2: sum_{i<j}(x_j - x_i) = sum_k (2k-15) x_k
        float2 t2 = make_float2(0.f, 0.f);
        #pragma unroll
        for (int k = 0; k < 16; k++) {
            const float w = (float)(2 * k - 15);
            t2.x = fmaf(w, v[k].x, t2.x);
            t2.y = fmaf(w, v[k].y, t2.y);
        }

        const float c1 = 1.0f / (16.0f * (float)NPIX);
        const float c2 = 1.0f / (240.0f * (float)NPIX);
        acc += (t1.x + t1.y) * c1 - (t2.x + t2.y) * c2;

        mbar_arrive(sb + MBAR_OFF + 24 + st * 8);             // empty (release)

        if (tid == 0) {
            const int j = i + STAGES;
            if (j < nt) {
                mbar_wait(sb + MBAR_OFF + 24 + st * 8, ((j / STAGES) + 1) & 1);
                issue_tile(preds, gt, bid + j * GRID, st, sb);
            }
        }
    }

    // Deterministic block reduction (16 warps)
    #pragma unroll
    for (int o = 16; o > 0; o >>= 1) acc += __shfl_down_sync(0xffffffffu, acc, o);
    __shared__ float s[NTHR / 32];
    if ((tid & 31) == 0) s[tid >> 5] = acc;
    __syncthreads();
    if (tid < 32) {
        float x = (tid < (NTHR / 32)) ? s[tid] : 0.f;
        #pragma unroll
        for (int o = 8; o > 0; o >>= 1) x += __shfl_down_sync(0xffffu, x, o);
        if (tid == 0) g_partials[bid] = x;
    }

    // Last-block final reduction (deterministic order; atomic only elects)
    __shared__ bool s_last;
    __threadfence();
    if (tid == 0) {
        unsigned int r = atomicAdd(&g_done, 1u);
        s_last = (r == (unsigned)(GRID - 1));
    }
    __syncthreads();
    if (s_last) {
        float a2 = (tid < GRID) ? __ldcg(&g_partials[tid]) : 0.f;
        #pragma unroll
        for (int o = 16; o > 0; o >>= 1) a2 += __shfl_down_sync(0xffffffffu, a2, o);
        __shared__ float s2[NTHR / 32];
        if ((tid & 31) == 0) s2[tid >> 5] = a2;
        __syncthreads();
        if (tid == 0) {
            float x = 0.f;
            #pragma unroll
            for (int w = 0; w < 5; w++) x += s2[w];   // GRID=148 -> warps 0..4 hold data
            out[0] = x;
            g_done = 0;                               // reset for graph replay
        }
    }
}

extern "C" void kernel_launch(void* const* d_in, const int* in_sizes, int n_in,
                              void* d_out, int out_size) {
    const float* preds = (const float*)d_in[0];
    const float* gt    = (const float*)d_in[1];
    float* out = (float*)d_out;
    (void)in_sizes; (void)n_in; (void)out_size;
    cudaFuncSetAttribute(crps_tma, cudaFuncAttributeMaxDynamicSharedMemorySize, SMEM_BYTES);
    crps_tma<<<GRID, NTHR, SMEM_BYTES>>>(preds, gt, out);
}

// round 6
// speedup vs baseline: 1.1385x; 1.1214x over previous
#include <cuda_runtime.h>
#include <cstdint>

// preds [B=8, N=16, C=4, H=128, W=256] f32, gt [8,4,128,256] f32, out scalar f32
#define CHW        131072
#define NCHW       (16 * CHW)
#define NPIX       1048576
#define GRID       148
#define NCONS      512                  // consumer threads (16 warps, float2 each)
#define NTHR       544                  // + 1 producer warp
#define TILE_PX    1024
#define NTILES     1024                 // NPIX / TILE_PX
#define TILE_B     4096
#define NSLICE     17                   // 16 preds + gt
#define STAGE_B    (NSLICE * TILE_B)    // 69632 B
#define STAGES     3
#define SMEM_BYTES (STAGES * STAGE_B + 64)
#define MBAR_OFF   (STAGES * STAGE_B)   // full[0..2] then empty[0..2], 8B each

__device__ float        g_partials[GRID];
__device__ unsigned int g_done = 0;

__device__ __forceinline__ uint32_t smem_u32(const void* p) {
    uint32_t a;
    asm("{ .reg .u64 t; cvta.to.shared.u64 t, %1; cvt.u32.u64 %0, t; }" : "=r"(a) : "l"(p));
    return a;
}
__device__ __forceinline__ void mbar_init(uint32_t m, uint32_t cnt) {
    asm volatile("mbarrier.init.shared.b64 [%0], %1;" :: "r"(m), "r"(cnt) : "memory");
}
__device__ __forceinline__ void mbar_expect_tx(uint32_t m, uint32_t bytes) {
    asm volatile("mbarrier.arrive.expect_tx.shared.b64 _, [%0], %1;" :: "r"(m), "r"(bytes) : "memory");
}
__device__ __forceinline__ void mbar_arrive(uint32_t m) {
    asm volatile("mbarrier.arrive.shared.b64 _, [%0];" :: "r"(m) : "memory");
}
__device__ __forceinline__ void mbar_wait(uint32_t m, uint32_t parity) {
    asm volatile(
        "{\n\t.reg .pred P;\n\t"
        "W%=:\n\t"
        "mbarrier.try_wait.parity.shared.b64 P, [%0], %1, 0x989680;\n\t"
        "@!P bra W%=;\n\t}"
        :: "r"(m), "r"(parity) : "memory");
}
__device__ __forceinline__ void bulk_g2s(uint32_t dst, const void* src, uint32_t bytes, uint32_t mbar) {
    asm volatile(
        "cp.async.bulk.shared::cta.global.mbarrier::complete_tx::bytes [%0], [%1], %2, [%3];"
        :: "r"(dst), "l"(src), "r"(bytes), "r"(mbar) : "memory");
}

__device__ __forceinline__ void cas2(float2 &a, float2 &b) {
    float2 lo, hi;
    lo.x = fminf(a.x, b.x); hi.x = fmaxf(a.x, b.x);
    lo.y = fminf(a.y, b.y); hi.y = fmaxf(a.y, b.y);
    a = lo; b = hi;
}

__device__ __forceinline__ void issue_tile(const float* preds, const float* gt,
                                           int tg, int st, uint32_t sb) {
    const int b   = tg >> 7;                    // 128 tiles per batch image
    const int chw = (tg & 127) * TILE_PX;
    const uint32_t stage = sb + st * STAGE_B;
    const uint32_t mbar_full = sb + MBAR_OFF + st * 8;
    mbar_expect_tx(mbar_full, NSLICE * TILE_B);
    #pragma unroll
    for (int n = 0; n < 16; n++)
        bulk_g2s(stage + n * TILE_B, preds + b * NCHW + n * CHW + chw, TILE_B, mbar_full);
    bulk_g2s(stage + 16 * TILE_B, gt + b * CHW + chw, TILE_B, mbar_full);
}

__global__ __launch_bounds__(NTHR) void crps_tma(const float* __restrict__ preds,
                                                 const float* __restrict__ gt,
                                                 float* __restrict__ out) {
    extern __shared__ char smem[];
    const uint32_t sb  = smem_u32(smem);
    const int tid = threadIdx.x;
    const int bid = blockIdx.x;

    if (tid == 0) {
        #pragma unroll
        for (int s = 0; s < STAGES; s++) {
            mbar_init(sb + MBAR_OFF + s * 8, 1);               // full: expect_tx + tx
            mbar_init(sb + MBAR_OFF + 24 + s * 8, NCONS / 32); // empty: 1 per consumer warp
        }
    }
    __syncthreads();

    const int nt = (NTILES - bid + GRID - 1) / GRID;           // 6 or 7 tiles
    float acc = 0.f;

    if (tid >= NCONS) {
        // ── Producer warp: owns all TMA issues; never computes ──
        if ((tid & 31) == 0) {
            const int pre = nt < STAGES ? nt : STAGES;
            for (int j = 0; j < pre; j++)
                issue_tile(preds, gt, bid + j * GRID, j, sb);
            for (int j = STAGES; j < nt; j++) {
                const int st = j % STAGES;
                mbar_wait(sb + MBAR_OFF + 24 + st * 8, ((j / STAGES) + 1) & 1);
                issue_tile(preds, gt, bid + j * GRID, st, sb);
            }
        }
    } else {
        // ── Consumers: 512 threads, 2 pixels each ──
        for (int i = 0; i < nt; i++) {
            const int st = i % STAGES;
            mbar_wait(sb + MBAR_OFF + st * 8, (i / STAGES) & 1);   // full

            const char* stage = smem + st * STAGE_B;
            const float2 g = reinterpret_cast<const float2*>(stage + 16 * TILE_B)[tid];
            float2 v[16];
            #pragma unroll
            for (int n = 0; n < 16; n++)
                v[n] = reinterpret_cast<const float2*>(stage + n * TILE_B)[tid];

            // term1 consumes every loaded value -> all LDS complete after this
            float2 t1 = make_float2(0.f, 0.f);
            #pragma unroll
            for (int n = 0; n < 16; n++) {
                t1.x += fabsf(v[n].x - g.x);
                t1.y += fabsf(v[n].y - g.y);
            }

            // Early stage release: data is register-resident now
            __syncwarp();
            if ((tid & 31) == 0) mbar_arrive(sb + MBAR_OFF + 24 + st * 8);

            // Green's 16-input 60-comparator sorting network (component-wise)
            cas2(v[0],v[1]);  cas2(v[2],v[3]);  cas2(v[4],v[5]);  cas2(v[6],v[7]);
            cas2(v[8],v[9]);  cas2(v[10],v[11]);cas2(v[12],v[13]);cas2(v[14],v[15]);
            cas2(v[0],v[2]);  cas2(v[4],v[6]);  cas2(v[8],v[10]); cas2(v[12],v[14]);
            cas2(v[1],v[3]);  cas2(v[5],v[7]);  cas2(v[9],v[11]); cas2(v[13],v[15]);
            cas2(v[0],v[4]);  cas2(v[8],v[12]); cas2(v[1],v[5]);  cas2(v[9],v[13]);
            cas2(v[2],v[6]);  cas2(v[10],v[14]);cas2(v[3],v[7]);  cas2(v[11],v[15]);
            cas2(v[0],v[8]);  cas2(v[1],v[9]);  cas2(v[2],v[10]); cas2(v[3],v[11]);
            cas2(v[4],v[12]); cas2(v[5],v[13]); cas2(v[6],v[14]); cas2(v[7],v[15]);
            cas2(v[5],v[10]); cas2(v[6],v[9]);  cas2(v[3],v[12]); cas2(v[13],v[14]);
            cas2(v[7],v[11]); cas2(v[1],v[2]);  cas2(v[4],v[8]);
            cas2(v[1],v[4]);  cas2(v[7],v[13]); cas2(v[2],v[8]);  cas2(v[11],v[14]);
            cas2(v[5],v[6]);  cas2(v[9],v[10]);
            cas2(v[2],v[4]);  cas2(v[11],v[13]);cas2(v[3],v[8]);  cas2(v[7],v[12]);
            cas2(v[6],v[8]);  cas2(v[10],v[12]);cas2(v[3],v[5]);  cas2(v[7],v[9]);
            cas2(v[3],v[4]);  cas2(v[5],v[6]);  cas2(v[7],v[8]);  cas2(v[9],v[10]);
            cas2(v[11],v[12]);
            cas2(v[6],v[7]);  cas2(v[8],v[9]);

            // term2: sum_{i<j}(x_j - x_i) = sum_k (2k-15) x_k
            float2 t2 = make_float2(0.f, 0.f);
            #pragma unroll
            for (int k = 0; k < 16; k++) {
                const float w = (float)(2 * k - 15);
                t2.x = fmaf(w, v[k].x, t2.x);
                t2.y = fmaf(w, v[k].y, t2.y);
            }

            const float c1 = 1.0f / (16.0f * (float)NPIX);
            const float c2 = 1.0f / (240.0f * (float)NPIX);
            acc += (t1.x + t1.y) * c1 - (t2.x + t2.y) * c2;
        }
    }

    // Deterministic block reduction (17 warps; producer contributes 0)
    #pragma unroll
    for (int o = 16; o > 0; o >>= 1) acc += __shfl_down_sync(0xffffffffu, acc, o);
    __shared__ float s[NTHR / 32];
    if ((tid & 31) == 0) s[tid >> 5] = acc;
    __syncthreads();
    if (tid < 32) {
        float x = (tid < (NTHR / 32)) ? s[tid] : 0.f;
        #pragma unroll
        for (int o = 16; o > 0; o >>= 1) x += __shfl_down_sync(0xffffffffu, x, o);
        if (tid == 0) g_partials[bid] = x;
    }

    // Last-block final reduction (deterministic order; atomic only elects)
    __shared__ bool s_last;
    __threadfence();
    if (tid == 0) {
        unsigned int r = atomicAdd(&g_done, 1u);
        s_last = (r == (unsigned)(GRID - 1));
    }
    __syncthreads();
    if (s_last) {
        float a2 = (tid < GRID) ? __ldcg(&g_partials[tid]) : 0.f;
        #pragma unroll
        for (int o = 16; o > 0; o >>= 1) a2 += __shfl_down_sync(0xffffffffu, a2, o);
        __shared__ float s2[NTHR / 32];
        if ((tid & 31) == 0) s2[tid >> 5] = a2;
        __syncthreads();
        if (tid == 0) {
            float x = 0.f;
            #pragma unroll
            for (int w = 0; w < 5; w++) x += s2[w];   // 148 threads span warps 0..4
            out[0] = x;
            g_done = 0;                               // reset for graph replay
        }
    }
}

extern "C" void kernel_launch(void* const* d_in, const int* in_sizes, int n_in,
                              void* d_out, int out_size) {
    const float* preds = (const float*)d_in[0];
    const float* gt    = (const float*)d_in[1];
    float* out = (float*)d_out;
    (void)in_sizes; (void)n_in; (void)out_size;
    cudaFuncSetAttribute(crps_tma, cudaFuncAttributeMaxDynamicSharedMemorySize, SMEM_BYTES);
    crps_tma<<<GRID, NTHR, SMEM_BYTES>>>(preds, gt, out);
}